// round 1
// baseline (speedup 1.0000x reference)
#include <cuda_runtime.h>
#include <math.h>

// Problem shape (fixed by setup_inputs): B=8, T=2048, C=1024
constexpr int kB = 8;
constexpr int kT = 2048;
constexpr int kC = 1024;
constexpr int kM = kB * kT;  // 16384 rows

// Scratch (no allocations allowed -> __device__ globals)
__device__ float g_key [(size_t)kM * kC];
__device__ float g_val [(size_t)kM * kC];
__device__ float g_r   [(size_t)kM * kC];
__device__ float g_rwkv[(size_t)kM * kC];

// ---------------------------------------------------------------------------
// Fused kernel: time-shift mixing + 3 GEMMs (key, value, sigmoid(receptance))
// out[b,t,d] = sum_c in[b,t,c] * W[d,c]
// Tile: 64(M) x 64(N) x 16(K), 256 threads, 4x4 microtile, 3 output sets.
// ---------------------------------------------------------------------------
__global__ __launch_bounds__(256, 2)
void gemm3_mix_kernel(const float* __restrict__ x,
                      const float* __restrict__ wk,
                      const float* __restrict__ wv,
                      const float* __restrict__ wr,
                      const float* __restrict__ mk,
                      const float* __restrict__ mv,
                      const float* __restrict__ mr)
{
    __shared__ __align__(16) float As[3][16][68];
    __shared__ __align__(16) float Bs[3][16][68];

    const int m0  = blockIdx.x * 64;
    const int n0  = blockIdx.y * 64;
    const int tid = threadIdx.x;
    const int tx  = tid & 15;        // 0..15  -> N microtile
    const int ty  = tid >> 4;        // 0..15  -> M microtile
    const int lr  = tid >> 2;        // loader row 0..63
    const int lc  = (tid & 3) * 4;   // loader col {0,4,8,12}

    float acc[3][4][4];
#pragma unroll
    for (int s = 0; s < 3; s++)
#pragma unroll
        for (int i = 0; i < 4; i++)
#pragma unroll
            for (int j = 0; j < 4; j++) acc[s][i][j] = 0.f;

    const int gm = m0 + lr;
    const bool is_t0 = ((gm & (kT - 1)) == 0);   // first timestep of a batch
    const float* xrow = x + (size_t)gm * kC;
    const float* prow = xrow - kC;               // not deref'd when is_t0
    const float* wkr  = wk + (size_t)(n0 + lr) * kC;
    const float* wvr  = wv + (size_t)(n0 + lr) * kC;
    const float* wrr  = wr + (size_t)(n0 + lr) * kC;

    for (int k0 = 0; k0 < kC; k0 += 16) {
        float4 xv  = *(const float4*)(xrow + k0 + lc);
        float4 pv  = is_t0 ? make_float4(0.f, 0.f, 0.f, 0.f)
                           : *(const float4*)(prow + k0 + lc);
        float4 mk4 = *(const float4*)(mk + k0 + lc);
        float4 mv4 = *(const float4*)(mv + k0 + lc);
        float4 mr4 = *(const float4*)(mr + k0 + lc);
        float4 bk  = *(const float4*)(wkr + k0 + lc);
        float4 bv  = *(const float4*)(wvr + k0 + lc);
        float4 br  = *(const float4*)(wrr + k0 + lc);

        const float* xe  = (const float*)&xv;
        const float* pe  = (const float*)&pv;
        const float* mke = (const float*)&mk4;
        const float* mve = (const float*)&mv4;
        const float* mre = (const float*)&mr4;
        const float* bke = (const float*)&bk;
        const float* bve = (const float*)&bv;
        const float* bre = (const float*)&br;

#pragma unroll
        for (int j = 0; j < 4; j++) {
            const float dx = xe[j] - pe[j];
            As[0][lc + j][lr] = fmaf(mke[j], dx, pe[j]);   // k_in
            As[1][lc + j][lr] = fmaf(mve[j], dx, pe[j]);   // v_in
            As[2][lc + j][lr] = fmaf(mre[j], dx, pe[j]);   // r_in
            Bs[0][lc + j][lr] = bke[j];
            Bs[1][lc + j][lr] = bve[j];
            Bs[2][lc + j][lr] = bre[j];
        }
        __syncthreads();

#pragma unroll
        for (int kk = 0; kk < 16; kk++) {
            float a[3][4], bb[3][4];
#pragma unroll
            for (int s = 0; s < 3; s++) {
                *(float4*)a[s]  = *(const float4*)&As[s][kk][ty * 4];
                *(float4*)bb[s] = *(const float4*)&Bs[s][kk][tx * 4];
            }
#pragma unroll
            for (int s = 0; s < 3; s++)
#pragma unroll
                for (int i = 0; i < 4; i++)
#pragma unroll
                    for (int j = 0; j < 4; j++)
                        acc[s][i][j] = fmaf(a[s][i], bb[s][j], acc[s][i][j]);
        }
        __syncthreads();
    }

#pragma unroll
    for (int i = 0; i < 4; i++) {
        const size_t off = (size_t)(m0 + ty * 4 + i) * kC + n0 + tx * 4;
        *(float4*)(g_key + off) = *(float4*)acc[0][i];
        *(float4*)(g_val + off) = *(float4*)acc[1][i];
        float4 rr;
        rr.x = 1.f / (1.f + __expf(-acc[2][i][0]));
        rr.y = 1.f / (1.f + __expf(-acc[2][i][1]));
        rr.z = 1.f / (1.f + __expf(-acc[2][i][2]));
        rr.w = 1.f / (1.f + __expf(-acc[2][i][3]));
        *(float4*)(g_r + off) = rr;
    }
}

// ---------------------------------------------------------------------------
// WKV scan: one thread per (b, c) channel, serial over T.
// Writes rwkv = sigmoid(r) * wkv directly.
// ---------------------------------------------------------------------------
__global__ void wkv_kernel(const float* __restrict__ td,
                           const float* __restrict__ tf)
{
    const int idx = blockIdx.x * blockDim.x + threadIdx.x;  // 0 .. B*C-1
    const int b = idx >> 10;          // / kC
    const int c = idx & (kC - 1);

    const float w = -__expf(td[c]);
    const float u = tf[c];

    const size_t base = ((size_t)b * kT) * kC + c;
    const float* kp = g_key + base;
    const float* vp = g_val + base;
    const float* rp = g_r   + base;
    float*       op = g_rwkv + base;

    float num = 0.f, den = 0.f, mx = -1e38f;
    float k = kp[0], v = vp[0], r = rp[0];

    for (int t = 0; t < kT; t++) {
        float kn = 0.f, vn = 0.f, rn = 0.f;
        if (t + 1 < kT) {                       // prefetch next step
            const size_t o = (size_t)(t + 1) * kC;
            kn = kp[o]; vn = vp[o]; rn = rp[o];
        }
        // output
        const float ku = k + u;
        const float mo = fmaxf(mx, ku);
        const float e1 = __expf(mx - mo);
        const float e2 = __expf(ku - mo);
        const float outv = __fdividef(fmaf(e1, num, e2 * v),
                                      fmaf(e1, den, e2));
        // state update
        const float mw  = mx + w;
        const float ms  = fmaxf(mw, k);
        const float e1s = __expf(mw - ms);
        const float e2s = __expf(k - ms);
        num = fmaf(e1s, num, e2s * v);
        den = fmaf(e1s, den, e2s);
        mx  = ms;

        op[(size_t)t * kC] = r * outv;
        k = kn; v = vn; r = rn;
    }
}

// ---------------------------------------------------------------------------
// Output GEMM: out = rwkv @ wo^T  (same tiling as above, single output)
// ---------------------------------------------------------------------------
__global__ __launch_bounds__(256, 2)
void gemm1_kernel(const float* __restrict__ W,
                  float* __restrict__ out)
{
    __shared__ __align__(16) float As[16][68];
    __shared__ __align__(16) float Bs[16][68];

    const int m0  = blockIdx.x * 64;
    const int n0  = blockIdx.y * 64;
    const int tid = threadIdx.x;
    const int tx  = tid & 15;
    const int ty  = tid >> 4;
    const int lr  = tid >> 2;
    const int lc  = (tid & 3) * 4;

    float acc[4][4];
#pragma unroll
    for (int i = 0; i < 4; i++)
#pragma unroll
        for (int j = 0; j < 4; j++) acc[i][j] = 0.f;

    const float* arow = g_rwkv + (size_t)(m0 + lr) * kC;
    const float* wrow = W + (size_t)(n0 + lr) * kC;

    for (int k0 = 0; k0 < kC; k0 += 16) {
        float4 av = *(const float4*)(arow + k0 + lc);
        float4 bv = *(const float4*)(wrow + k0 + lc);
        const float* ae = (const float*)&av;
        const float* be = (const float*)&bv;
#pragma unroll
        for (int j = 0; j < 4; j++) {
            As[lc + j][lr] = ae[j];
            Bs[lc + j][lr] = be[j];
        }
        __syncthreads();

#pragma unroll
        for (int kk = 0; kk < 16; kk++) {
            float a[4], bb[4];
            *(float4*)a  = *(const float4*)&As[kk][ty * 4];
            *(float4*)bb = *(const float4*)&Bs[kk][tx * 4];
#pragma unroll
            for (int i = 0; i < 4; i++)
#pragma unroll
                for (int j = 0; j < 4; j++)
                    acc[i][j] = fmaf(a[i], bb[j], acc[i][j]);
        }
        __syncthreads();
    }

#pragma unroll
    for (int i = 0; i < 4; i++) {
        const size_t off = (size_t)(m0 + ty * 4 + i) * kC + n0 + tx * 4;
        *(float4*)(out + off) = *(float4*)acc[i];
    }
}

// ---------------------------------------------------------------------------
// Launch
// ---------------------------------------------------------------------------
extern "C" void kernel_launch(void* const* d_in, const int* in_sizes, int n_in,
                              void* d_out, int out_size)
{
    const float* x  = (const float*)d_in[0];
    const float* wk = (const float*)d_in[1];
    const float* wv = (const float*)d_in[2];
    const float* wr = (const float*)d_in[3];
    const float* wo = (const float*)d_in[4];
    const float* td = (const float*)d_in[5];
    const float* tf = (const float*)d_in[6];
    const float* mk = (const float*)d_in[7];
    const float* mv = (const float*)d_in[8];
    const float* mr = (const float*)d_in[9];
    float* out = (float*)d_out;

    dim3 grid(kM / 64, kC / 64);   // 256 x 16
    gemm3_mix_kernel<<<grid, 256>>>(x, wk, wv, wr, mk, mv, mr);
    wkv_kernel<<<(kB * kC) / 128, 128>>>(td, tf);
    gemm1_kernel<<<grid, 256>>>(wo, out);
}

// round 3
// speedup vs baseline: 2.5995x; 2.5995x over previous
#include <cuda_runtime.h>
#include <cuda_bf16.h>
#include <cstdint>
#include <math.h>

// Problem shape (fixed): B=8, T=2048, C=1024
constexpr int kB = 8;
constexpr int kT = 2048;
constexpr int kC = 1024;
constexpr int kM = kB * kT;                 // 16384 rows
constexpr size_t kMC = (size_t)kM * kC;
constexpr size_t kCC = (size_t)kC * kC;

// ---------------------------------------------------------------------------
// Scratch (__device__ globals; no allocations allowed)
// ---------------------------------------------------------------------------
__device__ __nv_bfloat16 g_ah[3][kMC];   // mixed inputs (k,v,r), hi half
__device__ __nv_bfloat16 g_al[3][kMC];   // lo half
__device__ __nv_bfloat16 g_wh[3][kCC];   // wk,wv,wr hi
__device__ __nv_bfloat16 g_wl[3][kCC];   // lo
__device__ __nv_bfloat16 g_woh[kCC];
__device__ __nv_bfloat16 g_wol[kCC];
__device__ float         g_kvr[3][kMC];  // key, value, sigmoid(r)
__device__ __nv_bfloat16 g_rh[kMC];      // rwkv hi
__device__ __nv_bfloat16 g_rl[kMC];      // rwkv lo

// ---------------------------------------------------------------------------
// PTX helpers (baseline PTX only: works at .target sm_103)
// ---------------------------------------------------------------------------
__device__ __forceinline__ uint32_t smem_u32(const void* p) {
    uint32_t a;
    asm("{ .reg .u64 t; cvta.to.shared.u64 t, %1; cvt.u32.u64 %0, t; }"
        : "=r"(a) : "l"(p));
    return a;
}
__device__ __forceinline__ void cp_async16(uint32_t saddr, const void* gptr) {
    asm volatile("cp.async.ca.shared.global [%0], [%1], 16;"
                 :: "r"(saddr), "l"(gptr));
}
__device__ __forceinline__ void cp_commit() {
    asm volatile("cp.async.commit_group;");
}
template <int N>
__device__ __forceinline__ void cp_wait() {
    asm volatile("cp.async.wait_group %0;" :: "n"(N));
}
__device__ __forceinline__ void ldsm_x4(uint32_t* r, uint32_t addr) {
    asm volatile("ldmatrix.sync.aligned.m8n8.x4.shared.b16 {%0,%1,%2,%3}, [%4];"
                 : "=r"(r[0]), "=r"(r[1]), "=r"(r[2]), "=r"(r[3]) : "r"(addr));
}
__device__ __forceinline__ void ldsm_x2(uint32_t* r, uint32_t addr) {
    asm volatile("ldmatrix.sync.aligned.m8n8.x2.shared.b16 {%0,%1}, [%2];"
                 : "=r"(r[0]), "=r"(r[1]) : "r"(addr));
}
__device__ __forceinline__ void mma16816(float* d, const uint32_t* a, const uint32_t* b) {
    asm volatile("mma.sync.aligned.m16n8k16.row.col.f32.bf16.bf16.f32 "
                 "{%0,%1,%2,%3}, {%4,%5,%6,%7}, {%8,%9}, {%0,%1,%2,%3};"
                 : "+f"(d[0]), "+f"(d[1]), "+f"(d[2]), "+f"(d[3])
                 : "r"(a[0]), "r"(a[1]), "r"(a[2]), "r"(a[3]), "r"(b[0]), "r"(b[1]));
}

// ---------------------------------------------------------------------------
// split helpers
// ---------------------------------------------------------------------------
__device__ __forceinline__ void split1(float a, __nv_bfloat16& h, __nv_bfloat16& l) {
    h = __float2bfloat16_rn(a);
    l = __float2bfloat16_rn(a - __bfloat162float(h));
}
__device__ __forceinline__ void split4_store(const float* a, __nv_bfloat16* dh,
                                             __nv_bfloat16* dl, size_t off) {
    unsigned short uh[4], ul[4];
#pragma unroll
    for (int i = 0; i < 4; i++) {
        __nv_bfloat16 h, l;
        split1(a[i], h, l);
        uh[i] = __bfloat16_as_ushort(h);
        ul[i] = __bfloat16_as_ushort(l);
    }
    uint2 ph = make_uint2((uint32_t)uh[0] | ((uint32_t)uh[1] << 16),
                          (uint32_t)uh[2] | ((uint32_t)uh[3] << 16));
    uint2 pl = make_uint2((uint32_t)ul[0] | ((uint32_t)ul[1] << 16),
                          (uint32_t)ul[2] | ((uint32_t)ul[3] << 16));
    *(uint2*)(dh + off) = ph;
    *(uint2*)(dl + off) = pl;
}

// ---------------------------------------------------------------------------
// prep kernels
// ---------------------------------------------------------------------------
__global__ void prep_w_kernel(const float* __restrict__ wk, const float* __restrict__ wv,
                              const float* __restrict__ wr, const float* __restrict__ wo) {
    const int mat = blockIdx.y;
    const int row = blockIdx.x;
    const int c4  = threadIdx.x;
    const float* src = mat == 0 ? wk : mat == 1 ? wv : mat == 2 ? wr : wo;
    __nv_bfloat16* dh = mat < 3 ? g_wh[mat] : g_woh;
    __nv_bfloat16* dl = mat < 3 ? g_wl[mat] : g_wol;
    float4 v = ((const float4*)(src + (size_t)row * kC))[c4];
    split4_store((const float*)&v, dh, dl, (size_t)row * kC + c4 * 4);
}

__global__ void prep_a_kernel(const float* __restrict__ x,
                              const float* __restrict__ mk,
                              const float* __restrict__ mv,
                              const float* __restrict__ mr) {
    const int row = blockIdx.x;
    const int c4  = threadIdx.x;
    const float4 xv = ((const float4*)(x + (size_t)row * kC))[c4];
    float4 pv = make_float4(0.f, 0.f, 0.f, 0.f);
    if ((row & (kT - 1)) != 0)
        pv = ((const float4*)(x + (size_t)(row - 1) * kC))[c4];
    const float4 m0 = ((const float4*)mk)[c4];
    const float4 m1 = ((const float4*)mv)[c4];
    const float4 m2 = ((const float4*)mr)[c4];
    const float* xe = (const float*)&xv;
    const float* pe = (const float*)&pv;
    const float* me[3] = {(const float*)&m0, (const float*)&m1, (const float*)&m2};
    const size_t off = (size_t)row * kC + c4 * 4;
#pragma unroll
    for (int s = 0; s < 3; s++) {
        float a[4];
#pragma unroll
        for (int i = 0; i < 4; i++)
            a[i] = fmaf(me[s][i], xe[i] - pe[i], pe[i]);
        split4_store(a, g_ah[s], g_al[s], off);
    }
}

// ---------------------------------------------------------------------------
// bf16-split warp-MMA GEMM: out[m,n] = sum_k A[m,k]*B[n,k]
// CTA tile 128x128, K-chunk 32, 8 warps (warp tile 32x64), cp.async dbl-buffer
// ---------------------------------------------------------------------------
constexpr int kStrideB16 = 40;               // padded smem row stride (b16)
constexpr int kRowBytes  = kStrideB16 * 2;   // 80
constexpr int kTileBytes  = 128 * kRowBytes; // 10240
constexpr int kStageBytes = 4 * kTileBytes;  // 40960  (Ah, Al, Bh, Bl)
constexpr int kSmemBytes  = 2 * kStageBytes; // 81920
constexpr int OFF_AH = 0;
constexpr int OFF_AL = kTileBytes;
constexpr int OFF_BH = 2 * kTileBytes;
constexpr int OFF_BL = 3 * kTileBytes;

__device__ __forceinline__ void load_chunk(uint32_t sb, int stage, int tid,
                                           const __nv_bfloat16* Ah, const __nv_bfloat16* Al,
                                           const __nv_bfloat16* Bh, const __nv_bfloat16* Bl,
                                           int m0, int n0, int k0) {
    const uint32_t st = sb + stage * kStageBytes;
    const __nv_bfloat16* srcs[4] = {Ah, Al, Bh, Bl};
    const int bases[4] = {m0, m0, n0, n0};
    const uint32_t offs[4] = {OFF_AH, OFF_AL, OFF_BH, OFF_BL};
#pragma unroll
    for (int t = 0; t < 4; t++) {
#pragma unroll
        for (int rep = 0; rep < 2; rep++) {
            const int j = tid + rep * 256;         // 0..511
            const int row = j >> 2;
            const int seg = j & 3;
            const __nv_bfloat16* g = srcs[t] + (size_t)(bases[t] + row) * kC + k0 + seg * 8;
            cp_async16(st + offs[t] + row * kRowBytes + seg * 16, g);
        }
    }
}

__device__ __forceinline__ void gemm_body(const __nv_bfloat16* __restrict__ Ah,
                                          const __nv_bfloat16* __restrict__ Al,
                                          const __nv_bfloat16* __restrict__ Bh,
                                          const __nv_bfloat16* __restrict__ Bl,
                                          float* __restrict__ out,
                                          int epi_sigmoid) {
    extern __shared__ char smem[];
    const uint32_t sb = smem_u32(smem);
    const int tid  = threadIdx.x;
    const int wid  = tid >> 5;
    const int lane = tid & 31;
    const int wm   = wid & 3;        // 0..3  -> m offset wm*32
    const int wn   = wid >> 2;       // 0..1  -> n offset wn*64

    const int m0 = blockIdx.y * 128;
    const int n0 = blockIdx.x * 128;

    float acc[2][8][4];
#pragma unroll
    for (int mt = 0; mt < 2; mt++)
#pragma unroll
        for (int nt = 0; nt < 8; nt++)
#pragma unroll
            for (int i = 0; i < 4; i++) acc[mt][nt][i] = 0.f;

    // ldmatrix base addresses (within a stage, before stage offset)
    // A: row = wm*32 + mt*16 + (lane&15), colB16 = (lane>>4)*8 (+kk)
    const uint32_t aRowOff = (uint32_t)((wm * 32 + (lane & 15)) * kRowBytes + (lane >> 4) * 16);
    // B: row = wn*64 + nt*8 + (lane&7), colB16 = ((lane>>3)&1)*8 (+kk)
    const uint32_t bRowOff = (uint32_t)((wn * 64 + (lane & 7)) * kRowBytes + ((lane >> 3) & 1) * 16);

    load_chunk(sb, 0, tid, Ah, Al, Bh, Bl, m0, n0, 0);
    cp_commit();

    const int nChunks = kC / 32;   // 32
    for (int c = 0; c < nChunks; c++) {
        if (c + 1 < nChunks) {
            load_chunk(sb, (c + 1) & 1, tid, Ah, Al, Bh, Bl, m0, n0, (c + 1) * 32);
            cp_commit();
            cp_wait<1>();
        } else {
            cp_wait<0>();
        }
        __syncthreads();

        const uint32_t st = sb + (c & 1) * kStageBytes;
#pragma unroll
        for (int kk = 0; kk < 2; kk++) {          // two k16 steps per chunk
            const uint32_t kOff = kk * 32;        // 16 b16 = 32 bytes
            uint32_t ah[2][4], al[2][4], b[8][2];
#pragma unroll
            for (int mt = 0; mt < 2; mt++) {
                ldsm_x4(ah[mt], st + OFF_AH + aRowOff + mt * 16 * kRowBytes + kOff);
                ldsm_x4(al[mt], st + OFF_AL + aRowOff + mt * 16 * kRowBytes + kOff);
            }
#pragma unroll
            for (int nt = 0; nt < 8; nt++)
                ldsm_x2(b[nt], st + OFF_BH + bRowOff + nt * 8 * kRowBytes + kOff);
#pragma unroll
            for (int mt = 0; mt < 2; mt++)
#pragma unroll
                for (int nt = 0; nt < 8; nt++)
                    mma16816(acc[mt][nt], ah[mt], b[nt]);
#pragma unroll
            for (int mt = 0; mt < 2; mt++)
#pragma unroll
                for (int nt = 0; nt < 8; nt++)
                    mma16816(acc[mt][nt], al[mt], b[nt]);
#pragma unroll
            for (int nt = 0; nt < 8; nt++)
                ldsm_x2(b[nt], st + OFF_BL + bRowOff + nt * 8 * kRowBytes + kOff);
#pragma unroll
            for (int mt = 0; mt < 2; mt++)
#pragma unroll
                for (int nt = 0; nt < 8; nt++)
                    mma16816(acc[mt][nt], b[nt] == b[nt] ? ah[mt] : ah[mt], b[nt]);
        }
        __syncthreads();
    }

    // epilogue: c0,c1 -> row = lane>>2, cols (lane&3)*2 +{0,1}; c2,c3 -> row+8
    const int mBase = m0 + wm * 32;
    const int nBase = n0 + wn * 64;
#pragma unroll
    for (int mt = 0; mt < 2; mt++) {
#pragma unroll
        for (int nt = 0; nt < 8; nt++) {
            float* a4 = acc[mt][nt];
            if (epi_sigmoid) {
#pragma unroll
                for (int i = 0; i < 4; i++)
                    a4[i] = 1.f / (1.f + __expf(-a4[i]));
            }
            const int r0 = mBase + mt * 16 + (lane >> 2);
            const int cc = nBase + nt * 8 + (lane & 3) * 2;
            *(float2*)(out + (size_t)r0 * kC + cc)       = make_float2(a4[0], a4[1]);
            *(float2*)(out + (size_t)(r0 + 8) * kC + cc) = make_float2(a4[2], a4[3]);
        }
    }
}

__global__ __launch_bounds__(256, 2) void gemm3_kernel() {
    const int z = blockIdx.z;
    gemm_body(g_ah[z], g_al[z], g_wh[z], g_wl[z], g_kvr[z], z == 2 ? 1 : 0);
}
__global__ __launch_bounds__(256, 2) void gemm_out_kernel(float* __restrict__ out) {
    gemm_body(g_rh, g_rl, g_woh, g_wol, out, 0);
}

// ---------------------------------------------------------------------------
// WKV scan: one thread per (b,c). Triple-buffered 4-step group prefetch.
// ---------------------------------------------------------------------------
__global__ void wkv_kernel(const float* __restrict__ td, const float* __restrict__ tf) {
    const int idx = blockIdx.x * blockDim.x + threadIdx.x;  // 0..8191
    const int b = idx >> 10;
    const int c = idx & (kC - 1);

    const float w = -__expf(td[c]);
    const float u = tf[c];

    const size_t base = ((size_t)b * kT) * kC + c;
    const float* kp = g_kvr[0] + base;
    const float* vp = g_kvr[1] + base;
    const float* rp = g_kvr[2] + base;
    __nv_bfloat16* oh = g_rh + base;
    __nv_bfloat16* ol = g_rl + base;

    float kb[3][4], vb[3][4], rb[3][4];
#define LOADG(g, buf)                                           \
    {                                                           \
        _Pragma("unroll") for (int j = 0; j < 4; j++) {         \
            const size_t o = (size_t)((g) * 4 + j) * kC;        \
            kb[buf][j] = kp[o];                                 \
            vb[buf][j] = vp[o];                                 \
            rb[buf][j] = rp[o];                                 \
        }                                                       \
    }
    LOADG(0, 0);
    LOADG(1, 1);

    float num = 0.f, den = 0.f, mx = -1e38f;
    const int NG = kT / 4;  // 512
    for (int g = 0; g < NG; g++) {
        if (g + 2 < NG) {
            const int nb = (g + 2) % 3;
            LOADG(g + 2, nb);
        }
        const int cur = g % 3;
#pragma unroll
        for (int j = 0; j < 4; j++) {
            const float k = kb[cur][j], v = vb[cur][j], r = rb[cur][j];
            const float ku = k + u;
            const float mo = fmaxf(mx, ku);
            const float e1 = __expf(mx - mo);
            const float e2 = __expf(ku - mo);
            const float outv = __fdividef(fmaf(e1, num, e2 * v), fmaf(e1, den, e2));
            const float mw = mx + w;
            const float ms = fmaxf(mw, k);
            const float e1s = __expf(mw - ms);
            const float e2s = __expf(k - ms);
            num = fmaf(e1s, num, e2s * v);
            den = fmaf(e1s, den, e2s);
            mx = ms;

            const float o = r * outv;
            __nv_bfloat16 hb, lb;
            split1(o, hb, lb);
            const size_t toff = (size_t)(g * 4 + j) * kC;
            oh[toff] = hb;
            ol[toff] = lb;
        }
    }
#undef LOADG
}

// ---------------------------------------------------------------------------
// Launch
// ---------------------------------------------------------------------------
extern "C" void kernel_launch(void* const* d_in, const int* in_sizes, int n_in,
                              void* d_out, int out_size) {
    const float* x  = (const float*)d_in[0];
    const float* wk = (const float*)d_in[1];
    const float* wv = (const float*)d_in[2];
    const float* wr = (const float*)d_in[3];
    const float* wo = (const float*)d_in[4];
    const float* td = (const float*)d_in[5];
    const float* tf = (const float*)d_in[6];
    const float* mk = (const float*)d_in[7];
    const float* mv = (const float*)d_in[8];
    const float* mr = (const float*)d_in[9];
    float* out = (float*)d_out;

    cudaFuncSetAttribute(gemm3_kernel, cudaFuncAttributeMaxDynamicSharedMemorySize, kSmemBytes);
    cudaFuncSetAttribute(gemm_out_kernel, cudaFuncAttributeMaxDynamicSharedMemorySize, kSmemBytes);

    prep_w_kernel<<<dim3(kC, 4), 256>>>(wk, wv, wr, wo);
    prep_a_kernel<<<kM, 256>>>(x, mk, mv, mr);
    gemm3_kernel<<<dim3(kC / 128, kM / 128, 3), 256, kSmemBytes>>>();
    wkv_kernel<<<(kB * kC) / 128, 128>>>(td, tf);
    gemm_out_kernel<<<dim3(kC / 128, kM / 128), 256, kSmemBytes>>>(out);
}

// round 4
// speedup vs baseline: 3.3145x; 1.2750x over previous
#include <cuda_runtime.h>
#include <cuda_bf16.h>
#include <cstdint>
#include <math.h>

// Problem shape (fixed): B=8, T=2048, C=1024
constexpr int kB = 8;
constexpr int kT = 2048;
constexpr int kC = 1024;
constexpr int kM = kB * kT;                 // 16384 rows
constexpr size_t kMC = (size_t)kM * kC;
constexpr size_t kCC = (size_t)kC * kC;

// WKV blocked-scan config
constexpr int kSeg    = 16;                 // segments per sequence
constexpr int kSegLen = kT / kSeg;          // 128 steps per segment

// ---------------------------------------------------------------------------
// Scratch (__device__ globals; no allocations allowed)
// ---------------------------------------------------------------------------
__device__ __nv_bfloat16 g_ah[3][kMC];   // mixed inputs (k,v,r), hi half
__device__ __nv_bfloat16 g_al[3][kMC];   // lo half
__device__ __nv_bfloat16 g_wh[3][kCC];   // wk,wv,wr hi
__device__ __nv_bfloat16 g_wl[3][kCC];   // lo
__device__ __nv_bfloat16 g_woh[kCC];
__device__ __nv_bfloat16 g_wol[kCC];
__device__ float         g_kvr[3][kMC];  // key, value, sigmoid(r)
__device__ __nv_bfloat16 g_rh[kMC];      // rwkv hi
__device__ __nv_bfloat16 g_rl[kMC];      // rwkv lo
// segment summaries / exclusive prefixes: layout [(b*kSeg + seg)][c]
__device__ float g_segN[(size_t)kB * kSeg * kC];
__device__ float g_segD[(size_t)kB * kSeg * kC];
__device__ float g_segM[(size_t)kB * kSeg * kC];

// ---------------------------------------------------------------------------
// PTX helpers (baseline PTX only: works at .target sm_103)
// ---------------------------------------------------------------------------
__device__ __forceinline__ uint32_t smem_u32(const void* p) {
    uint32_t a;
    asm("{ .reg .u64 t; cvta.to.shared.u64 t, %1; cvt.u32.u64 %0, t; }"
        : "=r"(a) : "l"(p));
    return a;
}
__device__ __forceinline__ void cp_async16(uint32_t saddr, const void* gptr) {
    asm volatile("cp.async.ca.shared.global [%0], [%1], 16;"
                 :: "r"(saddr), "l"(gptr));
}
__device__ __forceinline__ void cp_commit() {
    asm volatile("cp.async.commit_group;");
}
template <int N>
__device__ __forceinline__ void cp_wait() {
    asm volatile("cp.async.wait_group %0;" :: "n"(N));
}
__device__ __forceinline__ void ldsm_x4(uint32_t* r, uint32_t addr) {
    asm volatile("ldmatrix.sync.aligned.m8n8.x4.shared.b16 {%0,%1,%2,%3}, [%4];"
                 : "=r"(r[0]), "=r"(r[1]), "=r"(r[2]), "=r"(r[3]) : "r"(addr));
}
__device__ __forceinline__ void ldsm_x2(uint32_t* r, uint32_t addr) {
    asm volatile("ldmatrix.sync.aligned.m8n8.x2.shared.b16 {%0,%1}, [%2];"
                 : "=r"(r[0]), "=r"(r[1]) : "r"(addr));
}
__device__ __forceinline__ void mma16816(float* d, const uint32_t* a, const uint32_t* b) {
    asm volatile("mma.sync.aligned.m16n8k16.row.col.f32.bf16.bf16.f32 "
                 "{%0,%1,%2,%3}, {%4,%5,%6,%7}, {%8,%9}, {%0,%1,%2,%3};"
                 : "+f"(d[0]), "+f"(d[1]), "+f"(d[2]), "+f"(d[3])
                 : "r"(a[0]), "r"(a[1]), "r"(a[2]), "r"(a[3]), "r"(b[0]), "r"(b[1]));
}

// ---------------------------------------------------------------------------
// split helpers
// ---------------------------------------------------------------------------
__device__ __forceinline__ void split1(float a, __nv_bfloat16& h, __nv_bfloat16& l) {
    h = __float2bfloat16_rn(a);
    l = __float2bfloat16_rn(a - __bfloat162float(h));
}
__device__ __forceinline__ void split4_store(const float* a, __nv_bfloat16* dh,
                                             __nv_bfloat16* dl, size_t off) {
    unsigned short uh[4], ul[4];
#pragma unroll
    for (int i = 0; i < 4; i++) {
        __nv_bfloat16 h, l;
        split1(a[i], h, l);
        uh[i] = __bfloat16_as_ushort(h);
        ul[i] = __bfloat16_as_ushort(l);
    }
    uint2 ph = make_uint2((uint32_t)uh[0] | ((uint32_t)uh[1] << 16),
                          (uint32_t)uh[2] | ((uint32_t)uh[3] << 16));
    uint2 pl = make_uint2((uint32_t)ul[0] | ((uint32_t)ul[1] << 16),
                          (uint32_t)ul[2] | ((uint32_t)ul[3] << 16));
    *(uint2*)(dh + off) = ph;
    *(uint2*)(dl + off) = pl;
}

// ---------------------------------------------------------------------------
// prep kernels
// ---------------------------------------------------------------------------
__global__ void prep_w_kernel(const float* __restrict__ wk, const float* __restrict__ wv,
                              const float* __restrict__ wr, const float* __restrict__ wo) {
    const int mat = blockIdx.y;
    const int row = blockIdx.x;
    const int c4  = threadIdx.x;
    const float* src = mat == 0 ? wk : mat == 1 ? wv : mat == 2 ? wr : wo;
    __nv_bfloat16* dh = mat < 3 ? g_wh[mat] : g_woh;
    __nv_bfloat16* dl = mat < 3 ? g_wl[mat] : g_wol;
    float4 v = ((const float4*)(src + (size_t)row * kC))[c4];
    split4_store((const float*)&v, dh, dl, (size_t)row * kC + c4 * 4);
}

__global__ void prep_a_kernel(const float* __restrict__ x,
                              const float* __restrict__ mk,
                              const float* __restrict__ mv,
                              const float* __restrict__ mr) {
    const int row = blockIdx.x;
    const int c4  = threadIdx.x;
    const float4 xv = ((const float4*)(x + (size_t)row * kC))[c4];
    float4 pv = make_float4(0.f, 0.f, 0.f, 0.f);
    if ((row & (kT - 1)) != 0)
        pv = ((const float4*)(x + (size_t)(row - 1) * kC))[c4];
    const float4 m0 = ((const float4*)mk)[c4];
    const float4 m1 = ((const float4*)mv)[c4];
    const float4 m2 = ((const float4*)mr)[c4];
    const float* xe = (const float*)&xv;
    const float* pe = (const float*)&pv;
    const float* me[3] = {(const float*)&m0, (const float*)&m1, (const float*)&m2};
    const size_t off = (size_t)row * kC + c4 * 4;
#pragma unroll
    for (int s = 0; s < 3; s++) {
        float a[4];
#pragma unroll
        for (int i = 0; i < 4; i++)
            a[i] = fmaf(me[s][i], xe[i] - pe[i], pe[i]);
        split4_store(a, g_ah[s], g_al[s], off);
    }
}

// ---------------------------------------------------------------------------
// bf16-split warp-MMA GEMM: out[m,n] = sum_k A[m,k]*B[n,k]
// CTA tile 128x128, K-chunk 32, 8 warps (warp tile 32x64), cp.async dbl-buffer
// ---------------------------------------------------------------------------
constexpr int kStrideB16 = 40;               // padded smem row stride (b16)
constexpr int kRowBytes  = kStrideB16 * 2;   // 80
constexpr int kTileBytes  = 128 * kRowBytes; // 10240
constexpr int kStageBytes = 4 * kTileBytes;  // 40960  (Ah, Al, Bh, Bl)
constexpr int kSmemBytes  = 2 * kStageBytes; // 81920
constexpr int OFF_AH = 0;
constexpr int OFF_AL = kTileBytes;
constexpr int OFF_BH = 2 * kTileBytes;
constexpr int OFF_BL = 3 * kTileBytes;

__device__ __forceinline__ void load_chunk(uint32_t sb, int stage, int tid,
                                           const __nv_bfloat16* Ah, const __nv_bfloat16* Al,
                                           const __nv_bfloat16* Bh, const __nv_bfloat16* Bl,
                                           int m0, int n0, int k0) {
    const uint32_t st = sb + stage * kStageBytes;
    const __nv_bfloat16* srcs[4] = {Ah, Al, Bh, Bl};
    const int bases[4] = {m0, m0, n0, n0};
    const uint32_t offs[4] = {OFF_AH, OFF_AL, OFF_BH, OFF_BL};
#pragma unroll
    for (int t = 0; t < 4; t++) {
#pragma unroll
        for (int rep = 0; rep < 2; rep++) {
            const int j = tid + rep * 256;         // 0..511
            const int row = j >> 2;
            const int seg = j & 3;
            const __nv_bfloat16* g = srcs[t] + (size_t)(bases[t] + row) * kC + k0 + seg * 8;
            cp_async16(st + offs[t] + row * kRowBytes + seg * 16, g);
        }
    }
}

__device__ __forceinline__ void gemm_body(const __nv_bfloat16* __restrict__ Ah,
                                          const __nv_bfloat16* __restrict__ Al,
                                          const __nv_bfloat16* __restrict__ Bh,
                                          const __nv_bfloat16* __restrict__ Bl,
                                          float* __restrict__ out,
                                          int epi_sigmoid) {
    extern __shared__ char smem[];
    const uint32_t sb = smem_u32(smem);
    const int tid  = threadIdx.x;
    const int wid  = tid >> 5;
    const int lane = tid & 31;
    const int wm   = wid & 3;        // m offset wm*32
    const int wn   = wid >> 2;       // n offset wn*64

    const int m0 = blockIdx.y * 128;
    const int n0 = blockIdx.x * 128;

    float acc[2][8][4];
#pragma unroll
    for (int mt = 0; mt < 2; mt++)
#pragma unroll
        for (int nt = 0; nt < 8; nt++)
#pragma unroll
            for (int i = 0; i < 4; i++) acc[mt][nt][i] = 0.f;

    const uint32_t aRowOff = (uint32_t)((wm * 32 + (lane & 15)) * kRowBytes + (lane >> 4) * 16);
    const uint32_t bRowOff = (uint32_t)((wn * 64 + (lane & 7)) * kRowBytes + ((lane >> 3) & 1) * 16);

    load_chunk(sb, 0, tid, Ah, Al, Bh, Bl, m0, n0, 0);
    cp_commit();

    const int nChunks = kC / 32;   // 32
    for (int c = 0; c < nChunks; c++) {
        if (c + 1 < nChunks) {
            load_chunk(sb, (c + 1) & 1, tid, Ah, Al, Bh, Bl, m0, n0, (c + 1) * 32);
            cp_commit();
            cp_wait<1>();
        } else {
            cp_wait<0>();
        }
        __syncthreads();

        const uint32_t st = sb + (c & 1) * kStageBytes;
#pragma unroll
        for (int kk = 0; kk < 2; kk++) {
            const uint32_t kOff = kk * 32;
            uint32_t ah[2][4], al[2][4], b[8][2];
#pragma unroll
            for (int mt = 0; mt < 2; mt++) {
                ldsm_x4(ah[mt], st + OFF_AH + aRowOff + mt * 16 * kRowBytes + kOff);
                ldsm_x4(al[mt], st + OFF_AL + aRowOff + mt * 16 * kRowBytes + kOff);
            }
#pragma unroll
            for (int nt = 0; nt < 8; nt++)
                ldsm_x2(b[nt], st + OFF_BH + bRowOff + nt * 8 * kRowBytes + kOff);
#pragma unroll
            for (int mt = 0; mt < 2; mt++)
#pragma unroll
                for (int nt = 0; nt < 8; nt++)
                    mma16816(acc[mt][nt], ah[mt], b[nt]);
#pragma unroll
            for (int mt = 0; mt < 2; mt++)
#pragma unroll
                for (int nt = 0; nt < 8; nt++)
                    mma16816(acc[mt][nt], al[mt], b[nt]);
#pragma unroll
            for (int nt = 0; nt < 8; nt++)
                ldsm_x2(b[nt], st + OFF_BL + bRowOff + nt * 8 * kRowBytes + kOff);
#pragma unroll
            for (int mt = 0; mt < 2; mt++)
#pragma unroll
                for (int nt = 0; nt < 8; nt++)
                    mma16816(acc[mt][nt], ah[mt], b[nt]);
        }
        __syncthreads();
    }

    const int mBase = m0 + wm * 32;
    const int nBase = n0 + wn * 64;
#pragma unroll
    for (int mt = 0; mt < 2; mt++) {
#pragma unroll
        for (int nt = 0; nt < 8; nt++) {
            float* a4 = acc[mt][nt];
            if (epi_sigmoid) {
#pragma unroll
                for (int i = 0; i < 4; i++)
                    a4[i] = 1.f / (1.f + __expf(-a4[i]));
            }
            const int r0 = mBase + mt * 16 + (lane >> 2);
            const int cc = nBase + nt * 8 + (lane & 3) * 2;
            *(float2*)(out + (size_t)r0 * kC + cc)       = make_float2(a4[0], a4[1]);
            *(float2*)(out + (size_t)(r0 + 8) * kC + cc) = make_float2(a4[2], a4[3]);
        }
    }
}

__global__ __launch_bounds__(256, 2) void gemm3_kernel() {
    const int z = blockIdx.z;
    gemm_body(g_ah[z], g_al[z], g_wh[z], g_wl[z], g_kvr[z], z == 2 ? 1 : 0);
}
__global__ __launch_bounds__(256, 2) void gemm_out_kernel(float* __restrict__ out) {
    gemm_body(g_rh, g_rl, g_woh, g_wol, out, 0);
}

// ---------------------------------------------------------------------------
// WKV blocked scan.
// State invariant: true_num = num * e^mx (likewise den).
// Segment transfer over L steps: true_out = e^{L*w} * true_in + local.
// ---------------------------------------------------------------------------

// Pass A: per-segment local summary from zero state.
__global__ void wkv_segA(const float* __restrict__ td) {
    const int c  = blockIdx.x * blockDim.x + threadIdx.x;   // 0..1023
    const int bs = blockIdx.y;                              // b*kSeg + seg
    const int b  = bs >> 4;
    const int sg = bs & (kSeg - 1);

    const float w = -__expf(td[c]);
    const size_t base = ((size_t)b * kT + (size_t)sg * kSegLen) * kC + c;
    const float* kp = g_kvr[0] + base;
    const float* vp = g_kvr[1] + base;

    float num = 0.f, den = 0.f, mx = -1e38f;
#pragma unroll 4
    for (int i = 0; i < kSegLen; i++) {
        const float k = kp[(size_t)i * kC];
        const float v = vp[(size_t)i * kC];
        const float mw = mx + w;
        const float ms = fmaxf(mw, k);
        const float e1 = __expf(mw - ms);
        const float e2 = __expf(k - ms);
        num = fmaf(e1, num, e2 * v);
        den = fmaf(e1, den, e2);
        mx = ms;
    }
    const size_t si = (size_t)bs * kC + c;
    g_segN[si] = num;
    g_segD[si] = den;
    g_segM[si] = mx;
}

// Prefix: serial exclusive scan over the kSeg segment summaries per channel.
__global__ void wkv_prefix(const float* __restrict__ td) {
    const int idx = blockIdx.x * blockDim.x + threadIdx.x;  // 0..8191
    const int b = idx >> 10;
    const int c = idx & (kC - 1);
    const float w = -__expf(td[c]);
    const float shift = (float)kSegLen * w;

    float N = 0.f, D = 0.f, M = -1e38f;
#pragma unroll
    for (int s = 0; s < kSeg; s++) {
        const size_t si = ((size_t)(b * kSeg + s)) * kC + c;
        const float n = g_segN[si];
        const float d = g_segD[si];
        const float m = g_segM[si];
        // store exclusive prefix (state entering this segment)
        g_segN[si] = N;
        g_segD[si] = D;
        g_segM[si] = M;
        // combine: advance carry by kSegLen steps, then add local
        const float Ms = M + shift;
        const float nm = fmaxf(Ms, m);
        const float ea = __expf(Ms - nm);
        const float eb = __expf(m - nm);
        N = fmaf(ea, N, eb * n);
        D = fmaf(ea, D, eb * d);
        M = nm;
    }
}

// Pass B: replay each segment from its exclusive-prefix state; emit outputs.
__global__ void wkv_segB(const float* __restrict__ td, const float* __restrict__ tf) {
    const int c  = blockIdx.x * blockDim.x + threadIdx.x;
    const int bs = blockIdx.y;
    const int b  = bs >> 4;
    const int sg = bs & (kSeg - 1);

    const float w = -__expf(td[c]);
    const float u = tf[c];

    const size_t si = (size_t)bs * kC + c;
    float num = g_segN[si];
    float den = g_segD[si];
    float mx  = g_segM[si];

    const size_t base = ((size_t)b * kT + (size_t)sg * kSegLen) * kC + c;
    const float* kp = g_kvr[0] + base;
    const float* vp = g_kvr[1] + base;
    const float* rp = g_kvr[2] + base;
    __nv_bfloat16* oh = g_rh + base;
    __nv_bfloat16* ol = g_rl + base;

#pragma unroll 4
    for (int i = 0; i < kSegLen; i++) {
        const size_t o = (size_t)i * kC;
        const float k = kp[o];
        const float v = vp[o];
        const float r = rp[o];
        // output at this step
        const float ku = k + u;
        const float mo = fmaxf(mx, ku);
        const float e1 = __expf(mx - mo);
        const float e2 = __expf(ku - mo);
        const float outv = __fdividef(fmaf(e1, num, e2 * v), fmaf(e1, den, e2));
        // state update
        const float mw = mx + w;
        const float ms = fmaxf(mw, k);
        const float e1s = __expf(mw - ms);
        const float e2s = __expf(k - ms);
        num = fmaf(e1s, num, e2s * v);
        den = fmaf(e1s, den, e2s);
        mx = ms;

        const float ov = r * outv;
        __nv_bfloat16 hb, lb;
        split1(ov, hb, lb);
        oh[o] = hb;
        ol[o] = lb;
    }
}

// ---------------------------------------------------------------------------
// Launch
// ---------------------------------------------------------------------------
extern "C" void kernel_launch(void* const* d_in, const int* in_sizes, int n_in,
                              void* d_out, int out_size) {
    const float* x  = (const float*)d_in[0];
    const float* wk = (const float*)d_in[1];
    const float* wv = (const float*)d_in[2];
    const float* wr = (const float*)d_in[3];
    const float* wo = (const float*)d_in[4];
    const float* td = (const float*)d_in[5];
    const float* tf = (const float*)d_in[6];
    const float* mk = (const float*)d_in[7];
    const float* mv = (const float*)d_in[8];
    const float* mr = (const float*)d_in[9];
    float* out = (float*)d_out;

    cudaFuncSetAttribute(gemm3_kernel, cudaFuncAttributeMaxDynamicSharedMemorySize, kSmemBytes);
    cudaFuncSetAttribute(gemm_out_kernel, cudaFuncAttributeMaxDynamicSharedMemorySize, kSmemBytes);

    prep_w_kernel<<<dim3(kC, 4), 256>>>(wk, wv, wr, wo);
    prep_a_kernel<<<kM, 256>>>(x, mk, mv, mr);
    gemm3_kernel<<<dim3(kC / 128, kM / 128, 3), 256, kSmemBytes>>>();

    dim3 wgrid(kC / 256, kB * kSeg);   // (4, 128)
    wkv_segA<<<wgrid, 256>>>(td);
    wkv_prefix<<<(kB * kC) / 256, 256>>>(td);
    wkv_segB<<<wgrid, 256>>>(td, tf);

    gemm_out_kernel<<<dim3(kC / 128, kM / 128), 256, kSmemBytes>>>(out);
}